// round 5
// baseline (speedup 1.0000x reference)
#include <cuda_runtime.h>
#include <cuda_bf16.h>
#include <cstdint>

// Problem constants (fixed by the dataset)
#define B_DIM 32
#define L_DIM 256
#define H_DIM 512
#define H4    (H_DIM / 4)      // 128 float4 per row
#define ZFPB  16               // frames per zero-fill block

// Scratch (tiny): exclusive cumsum start per source position, total per batch
__device__ int g_start[B_DIM * L_DIM];
__device__ int g_total[B_DIM];

// ---------------------------------------------------------------------------
// Kernel 1: per-batch cumsum of durations -> g_start (exclusive), g_total,
// and the mask floats written directly into d_out's mask region.
// One block per batch, 256 threads (== L).
// ---------------------------------------------------------------------------
__global__ void k_prep(const int* __restrict__ dur,
                       float* __restrict__ mask_out,   // d_out + B*T*H
                       int T) {
    const int b = blockIdx.x;
    const int i = threadIdx.x;          // encoder position 0..255
    __shared__ int s_warp[8];

    int d = dur[b * L_DIM + i];

    // Warp inclusive scan
    int v = d;
    const int lane = i & 31;
    const int wid  = i >> 5;
    #pragma unroll
    for (int off = 1; off < 32; off <<= 1) {
        int n = __shfl_up_sync(0xffffffffu, v, off);
        if (lane >= off) v += n;
    }
    if (lane == 31) s_warp[wid] = v;
    __syncthreads();
    if (wid == 0) {
        int w = (lane < 8) ? s_warp[lane] : 0;
        #pragma unroll
        for (int off = 1; off < 8; off <<= 1) {
            int n = __shfl_up_sync(0xffffffffu, w, off);
            if (lane >= off) w += n;
        }
        if (lane < 8) s_warp[lane] = w;
    }
    __syncthreads();

    const int incl  = v + ((wid > 0) ? s_warp[wid - 1] : 0);
    const int total = s_warp[7];
    const int start = incl - d;

    g_start[b * L_DIM + i] = start;
    if (i == 0) g_total[b] = total;

    // Mask output (float 1.0/0.0 matches int32 reference numerically)
    float* mrow = mask_out + (size_t)b * T;
    for (int t = i; t < T; t += L_DIM)
        mrow[t] = (t < total) ? 1.0f : 0.0f;
}

// ---------------------------------------------------------------------------
// Kernel 2: source-major copy. One block per (b, i) source position;
// 128 threads each read ONE float4 of the source row (read exactly once
// chip-wide -> 16MB total reads), then store it to the d consecutive
// output frames [start, start+d). Stores are independent + fully coalesced
// (warp writes 512B contiguous per frame).
// ---------------------------------------------------------------------------
__global__ void __launch_bounds__(H4, 8)
k_copy(const float4* __restrict__ x4,
       const int*    __restrict__ dur,
       float4*       __restrict__ out4,
       int T) {
    const int i   = blockIdx.x;
    const int b   = blockIdx.y;
    const int pos = b * L_DIM + i;

    const int d = dur[pos];            // uniform across block (broadcast)
    if (d == 0) return;
    const int start = g_start[pos];    // uniform (broadcast)

    const float4 v = __ldg(&x4[(size_t)pos * H4 + threadIdx.x]);

    float4* o = out4 + ((size_t)b * T + start) * H4 + threadIdx.x;
    #pragma unroll 4
    for (int k = 0; k < d; ++k)
        o[(size_t)k * H4] = v;
}

// ---------------------------------------------------------------------------
// Kernel 3: zero-fill masked tail frames (t >= total_b). Blocks entirely in
// the active region exit after one broadcast load. grid = (ceil(T/ZFPB), B).
// ---------------------------------------------------------------------------
__global__ void __launch_bounds__(256, 4)
k_zero(float4* __restrict__ out4, int T) {
    const int b     = blockIdx.y;
    const int t0    = blockIdx.x * ZFPB;
    const int total = g_total[b];
    if (t0 + ZFPB <= total) return;    // fully active: nothing to zero

    const int tid = threadIdx.x;
    const int c   = tid & (H4 - 1);
    int t = t0 + (tid >> 7);           // two frame lanes per block

    const float4 z = make_float4(0.f, 0.f, 0.f, 0.f);
    #pragma unroll
    for (int k = 0; k < ZFPB / 2; ++k, t += 2)
        if (t >= total && t < T)
            out4[((size_t)b * T + t) * H4 + c] = z;
}

// ---------------------------------------------------------------------------
extern "C" void kernel_launch(void* const* d_in, const int* in_sizes, int n_in,
                              void* d_out, int out_size) {
    const float* x   = (const float*)d_in[0];   // (B, L, H) float32
    const int*   dur = (const int*)d_in[1];     // (B, L)    int32

    // out_size = B*T*(H+1)  =>  T
    const int T = out_size / (B_DIM * (H_DIM + 1));

    float* out      = (float*)d_out;                          // (B, T, H)
    float* mask_out = out + (size_t)B_DIM * T * H_DIM;        // (B, T)

    k_prep<<<B_DIM, L_DIM>>>(dur, mask_out, T);

    dim3 gcopy(L_DIM, B_DIM);
    k_copy<<<gcopy, H4>>>((const float4*)x, dur, (float4*)out, T);

    dim3 gzero((T + ZFPB - 1) / ZFPB, B_DIM);
    k_zero<<<gzero, 256>>>((float4*)out, T);

    (void)in_sizes; (void)n_in;
}